// round 2
// baseline (speedup 1.0000x reference)
#include <cuda_runtime.h>
#include <cuda_bf16.h>
#include <cstdint>

constexpr int B = 8;
constexpr int X = 2048;
constexpr int Y = 2048;
constexpr int H = 1024;

constexpr int NCH = 32;        // Y-chunks
constexpr int YC  = Y / NCH;   // 64 rows per chunk

// Scratch (allocation-free __device__ globals)
__device__ float g_o  [B * H];   // unnormalized sum_y exp(sq) * v
__device__ float g_sum[B];       // sum_y exp(sq)

// -------------------------------------------------------------------------
// K0: zero accumulators (graph replays re-enter, must reset every call)
// -------------------------------------------------------------------------
__global__ void k_init() {
    const int i = blockIdx.x * 256 + threadIdx.x;
    if (i < B * H) g_o[i] = 0.0f;
    if (i < B)     g_sum[i] = 0.0f;
}

// -------------------------------------------------------------------------
// K1 (fused): per-chunk — sq = q·Wq, e = exp(sq) (no max-sub: |sq|<~5),
// then o_partial[h] = sum_y e[y] * v[y,h], atomically merged into g_o.
// grid (B, NCH), 256 threads.
// -------------------------------------------------------------------------
__global__ __launch_bounds__(256) void k_main(const float* __restrict__ q,
                                              const float* __restrict__ v,
                                              const float* __restrict__ W) {
    const int b = blockIdx.x;
    const int c = blockIdx.y;
    const int t = threadIdx.x;
    const int warp = t >> 5;
    const int lane = t & 31;

    __shared__ float wq[H];          // 4 KB
    __shared__ float e[YC];          // 256 B
    __shared__ float s_sum;

    for (int i = t; i < H; i += 256) wq[i] = W[H + i];
    if (t == 0) s_sum = 0.0f;
    __syncthreads();

    // Phase 1: one warp per row, 8 rows per pass, 8 passes over YC=64 rows
    const size_t rowbase = (size_t)b * Y + (size_t)c * YC;
    const float4* w4 = reinterpret_cast<const float4*>(wq);
#pragma unroll
    for (int pass = 0; pass < YC / 8; ++pass) {
        const int r = pass * 8 + warp;                  // local row 0..63
        const float4* qr = reinterpret_cast<const float4*>(q + (rowbase + r) * H);
        float acc = 0.f;
#pragma unroll
        for (int i = 0; i < (H / 4) / 32; ++i) {        // 8 float4 per lane
            float4 a  = qr[lane + i * 32];
            float4 wv = w4[lane + i * 32];
            acc += a.x * wv.x + a.y * wv.y + a.z * wv.z + a.w * wv.w;
        }
#pragma unroll
        for (int o = 16; o; o >>= 1) acc += __shfl_xor_sync(0xFFFFFFFFu, acc, o);
        if (lane == 0) {
            const float ev = __expf(acc);
            e[r] = ev;
            atomicAdd(&s_sum, ev);
        }
    }
    __syncthreads();
    if (t == 0) atomicAdd(&g_sum[b], s_sum);

    // Phase 2: thread t owns float4 column t (covers all H=1024), stream YC rows
    const float4* vb = reinterpret_cast<const float4*>(v + rowbase * H) + t;
    float4 acc = make_float4(0.f, 0.f, 0.f, 0.f);
#pragma unroll 4
    for (int y = 0; y < YC; ++y) {
        const float4 vv = vb[(size_t)y * (H / 4)];
        const float  ey = e[y];
        acc.x += ey * vv.x; acc.y += ey * vv.y;
        acc.z += ey * vv.z; acc.w += ey * vv.w;
    }
    float* o = &g_o[b * H + t * 4];
    atomicAdd(o + 0, acc.x);
    atomicAdd(o + 1, acc.y);
    atomicAdd(o + 2, acc.z);
    atomicAdd(o + 3, acc.w);
}

// -------------------------------------------------------------------------
// K2: out[b,x,h] = g_o[b,h] / g_sum[b].  Register-held value, 32 row-stores
// per thread. grid (B, X/XROWS), 256 threads.
// -------------------------------------------------------------------------
constexpr int XROWS = 32;

__global__ __launch_bounds__(256) void k_bcast(float* __restrict__ out) {
    const int b  = blockIdx.x;
    const int xs = blockIdx.y;
    const int t  = threadIdx.x;

    const float inv = 1.0f / g_sum[b];
    float4 val = reinterpret_cast<const float4*>(&g_o[b * H])[t];
    val.x *= inv; val.y *= inv; val.z *= inv; val.w *= inv;

    float4* o4 = reinterpret_cast<float4*>(out) +
                 ((size_t)b * X + (size_t)xs * XROWS) * (H / 4) + t;
#pragma unroll
    for (int x = 0; x < XROWS; ++x)
        o4[(size_t)x * (H / 4)] = val;
}

// -------------------------------------------------------------------------
// Inputs: q (B,Y,H) f32, k [UNUSED], v (B,Y,H) f32, W (2H,) f32, b [UNUSED]
// -------------------------------------------------------------------------
extern "C" void kernel_launch(void* const* d_in, const int* in_sizes, int n_in,
                              void* d_out, int out_size) {
    const float* q = (const float*)d_in[0];
    const float* v = (const float*)d_in[2];
    const float* W = (const float*)d_in[3];
    float* out = (float*)d_out;

    k_init<<<(B * H + 255) / 256, 256>>>();
    dim3 gm(B, NCH);
    k_main<<<gm, 256>>>(q, v, W);
    dim3 gb(B, X / XROWS);
    k_bcast<<<gb, 256>>>(out);
}

// round 4
// speedup vs baseline: 1.0735x; 1.0735x over previous
#include <cuda_runtime.h>
#include <cuda_bf16.h>
#include <cstdint>

constexpr int B = 8;
constexpr int X = 2048;
constexpr int Y = 2048;
constexpr int H = 1024;

constexpr int NCH = 64;        // Y-chunks per batch
constexpr int YC  = Y / NCH;   // 32 rows per chunk

// Scratch (allocation-free __device__ globals). Written fresh each call
// by plain stores -> no init kernel needed.
__device__ float g_part[B * NCH * H];   // 2 MB: per-chunk weighted v-sums
__device__ float g_psum[B * NCH];       // per-chunk exp-sums
__device__ float g_o   [B * H];         // normalized output row per batch

// -------------------------------------------------------------------------
// K1: per chunk (b,c): e[y] = exp(q[b,y,:]·Wq)  (shift-invariance: sk & bias
// cancel; |sq| small so no max-subtraction needed), then
// g_part[chunk][h] = sum_y e[y] * v[b,y,h];  g_psum[chunk] = sum_y e[y].
// grid = B*NCH = 512 blocks, 256 threads. Pure stores, no atomics.
// -------------------------------------------------------------------------
__global__ __launch_bounds__(256) void k_part(const float* __restrict__ q,
                                              const float* __restrict__ v,
                                              const float* __restrict__ W) {
    const int id   = blockIdx.x;          // 0..511
    const int b    = id >> 6;
    const int c    = id & (NCH - 1);
    const int t    = threadIdx.x;
    const int warp = t >> 5;
    const int lane = t & 31;

    __shared__ float wq[H];               // 4 KB
    __shared__ float e[YC];
    __shared__ float wsum[8];

    for (int i = t; i < H; i += 256) wq[i] = W[H + i];
    __syncthreads();

    const size_t rowbase = (size_t)b * Y + (size_t)c * YC;
    const float4* w4 = reinterpret_cast<const float4*>(wq);

    // Phase 1: warp-per-row dot products, YC/8 = 4 passes
    float mysum = 0.0f;
#pragma unroll
    for (int p = 0; p < YC / 8; ++p) {
        const int r = p * 8 + warp;
        const float4* qr = reinterpret_cast<const float4*>(q + (rowbase + r) * H);
        float acc = 0.0f;
#pragma unroll
        for (int i = 0; i < 8; ++i) {                 // 8 float4 per lane
            const float4 a  = __ldcs(&qr[lane + i * 32]);
            const float4 wv = w4[lane + i * 32];
            acc += a.x * wv.x + a.y * wv.y + a.z * wv.z + a.w * wv.w;
        }
#pragma unroll
        for (int o = 16; o; o >>= 1) acc += __shfl_xor_sync(0xFFFFFFFFu, acc, o);
        if (lane == 0) {
            const float ev = __expf(acc);
            e[r] = ev;
            mysum += ev;
        }
    }
    if (lane == 0) wsum[warp] = mysum;
    __syncthreads();

    // Phase 2: thread t owns float4 column t; stream YC rows of v
    const float4* vb = reinterpret_cast<const float4*>(v + rowbase * H) + t;
    float4 acc = make_float4(0.f, 0.f, 0.f, 0.f);
#pragma unroll 8
    for (int y = 0; y < YC; ++y) {
        const float4 vv = __ldcs(&vb[(size_t)y * (H / 4)]);
        const float  ey = e[y];
        acc.x += ey * vv.x; acc.y += ey * vv.y;
        acc.z += ey * vv.z; acc.w += ey * vv.w;
    }
    reinterpret_cast<float4*>(&g_part[(size_t)id * H])[t] = acc;

    if (t == 0) {
        float s = 0.f;
#pragma unroll
        for (int w = 0; w < 8; ++w) s += wsum[w];
        g_psum[id] = s;
    }
}

// -------------------------------------------------------------------------
// K1.5: g_o[b,h] = (sum_c g_part[b,c,h]) / (sum_c g_psum[b,c]).
// grid = 32 blocks (b*4 + hblk), 256 threads. All data L2-hot.
// -------------------------------------------------------------------------
__global__ __launch_bounds__(256) void k_reduce() {
    const int bx = blockIdx.x;            // 0..31
    const int b  = bx >> 2;
    const int h  = (bx & 3) * 256 + threadIdx.x;

    __shared__ float ssum[NCH];
    if (threadIdx.x < NCH) ssum[threadIdx.x] = g_psum[b * NCH + threadIdx.x];
    __syncthreads();

    float s = 0.f;
#pragma unroll
    for (int c = 0; c < NCH; ++c) s += ssum[c];

    float acc = 0.f;
#pragma unroll 8
    for (int c = 0; c < NCH; ++c)
        acc += g_part[((size_t)(b * NCH + c)) * H + h];

    g_o[b * H + h] = acc / s;
}

// -------------------------------------------------------------------------
// K2: out[b,x,:] = g_o[b,:] broadcast over x. Register-held float4,
// 32 streaming row-stores per thread. grid = 512 blocks, 256 threads.
// -------------------------------------------------------------------------
constexpr int XROWS = 32;

__global__ __launch_bounds__(256) void k_bcast(float* __restrict__ out) {
    const int bid  = blockIdx.x;          // 0..511
    const int b    = bid >> 6;
    const int slab = bid & 63;

    const float4 val = reinterpret_cast<const float4*>(&g_o[b * H])[threadIdx.x];

    float4* o4 = reinterpret_cast<float4*>(out) +
                 ((size_t)b * X + (size_t)slab * XROWS) * (H / 4) + threadIdx.x;
#pragma unroll
    for (int x = 0; x < XROWS; ++x)
        __stcs(&o4[(size_t)x * (H / 4)], val);
}

// -------------------------------------------------------------------------
// Inputs: q (B,Y,H) f32, k [UNUSED - cancels in softmax], v (B,Y,H) f32,
// W (2H,) f32, b [UNUSED - cancels]. Output (B,X,H) f32.
// -------------------------------------------------------------------------
extern "C" void kernel_launch(void* const* d_in, const int* in_sizes, int n_in,
                              void* d_out, int out_size) {
    const float* q = (const float*)d_in[0];
    const float* v = (const float*)d_in[2];
    const float* W = (const float*)d_in[3];
    float* out = (float*)d_out;

    k_part  <<<B * NCH, 256>>>(q, v, W);
    k_reduce<<<B * 4,   256>>>();
    k_bcast <<<B * 64,  256>>>(out);
}

// round 5
// speedup vs baseline: 1.1237x; 1.0468x over previous
#include <cuda_runtime.h>
#include <cuda_bf16.h>
#include <cstdint>

constexpr int B = 8;
constexpr int X = 2048;
constexpr int Y = 2048;
constexpr int H = 1024;

constexpr int NCH = 64;        // Y-chunks per batch
constexpr int YC  = Y / NCH;   // 32 rows per chunk
constexpr int RPW = YC / 8;    // 4 rows per warp

// Scratch (allocation-free __device__ globals). Written fresh each call.
__device__ float g_part[B * NCH * H];   // 2 MB per-chunk weighted v-sums
__device__ float g_psum[B * NCH];       // per-chunk exp-sums
__device__ float g_o   [B * H];         // normalized output row per batch

// -------------------------------------------------------------------------
// K1: warp-local fused dot+exp+weighted-sum. Each warp owns RPW=4 rows:
//   s = q[row]·Wq  (xor-reduce so ALL lanes hold s)  ->  e = exp(s)
//   acc[h] += e * v[row,h]   (8 float4 regs cover H=1024 per warp)
// No block barrier in the mainloop -> q-loads of row r+1 overlap v-FMAs of
// row r; LSU pipeline stays full. Single final fold through shared.
// -------------------------------------------------------------------------
__global__ __launch_bounds__(256) void k_part(const float* __restrict__ q,
                                              const float* __restrict__ v,
                                              const float* __restrict__ W) {
    const int id   = blockIdx.x;          // 0..511
    const int b    = id >> 6;
    const int c    = id & (NCH - 1);
    const int t    = threadIdx.x;
    const int warp = t >> 5;
    const int lane = t & 31;

    __shared__ float wq[H];               // 4 KB
    __shared__ float4 red[8 * (H / 4)];   // 32 KB fold buffer
    __shared__ float wsum[8];

    for (int i = t; i < H; i += 256) wq[i] = W[H + i];
    __syncthreads();

    const size_t rowbase = (size_t)b * Y + ((size_t)c * YC + warp * RPW);
    const float4* w4 = reinterpret_cast<const float4*>(wq);

    float4 acc[8];
#pragma unroll
    for (int i = 0; i < 8; ++i) acc[i] = make_float4(0.f, 0.f, 0.f, 0.f);
    float esum = 0.0f;

#pragma unroll
    for (int p = 0; p < RPW; ++p) {
        const float4* qr = reinterpret_cast<const float4*>(q + (rowbase + p) * H);
        float s = 0.0f;
#pragma unroll
        for (int i = 0; i < 8; ++i) {
            const float4 a  = __ldcs(&qr[lane + i * 32]);
            const float4 wv = w4[lane + i * 32];
            s += a.x * wv.x + a.y * wv.y + a.z * wv.z + a.w * wv.w;
        }
#pragma unroll
        for (int o = 16; o; o >>= 1) s += __shfl_xor_sync(0xFFFFFFFFu, s, o);
        const float e = __expf(s);        // identical in every lane
        esum += e;

        const float4* vr = reinterpret_cast<const float4*>(v + (rowbase + p) * H);
#pragma unroll
        for (int i = 0; i < 8; ++i) {
            const float4 vv = __ldcs(&vr[lane + i * 32]);
            acc[i].x += e * vv.x; acc[i].y += e * vv.y;
            acc[i].z += e * vv.z; acc[i].w += e * vv.w;
        }
    }

    // Fold 8 warps' accumulators
    float4* slab = &red[warp * (H / 4)];
#pragma unroll
    for (int i = 0; i < 8; ++i) slab[lane + i * 32] = acc[i];
    if (lane == 0) wsum[warp] = esum;
    __syncthreads();

    float4 tot = make_float4(0.f, 0.f, 0.f, 0.f);
#pragma unroll
    for (int w = 0; w < 8; ++w) {
        const float4 x = red[w * (H / 4) + t];
        tot.x += x.x; tot.y += x.y; tot.z += x.z; tot.w += x.w;
    }
    reinterpret_cast<float4*>(&g_part[(size_t)id * H])[t] = tot;

    if (t == 0) {
        float s = 0.f;
#pragma unroll
        for (int w = 0; w < 8; ++w) s += wsum[w];
        g_psum[id] = s;
    }
}

// -------------------------------------------------------------------------
// K1.5: g_o[b,h] = (sum_c g_part[b,c,h]) / (sum_c g_psum[b,c]).  L2-hot.
// -------------------------------------------------------------------------
__global__ __launch_bounds__(256) void k_reduce() {
    const int bx = blockIdx.x;            // 0..31
    const int b  = bx >> 2;
    const int h  = (bx & 3) * 256 + threadIdx.x;

    __shared__ float ssum[NCH];
    if (threadIdx.x < NCH) ssum[threadIdx.x] = g_psum[b * NCH + threadIdx.x];
    __syncthreads();

    float s = 0.f;
#pragma unroll
    for (int c = 0; c < NCH; ++c) s += ssum[c];

    float acc = 0.f;
#pragma unroll 8
    for (int c = 0; c < NCH; ++c)
        acc += g_part[((size_t)(b * NCH + c)) * H + h];

    g_o[b * H + h] = acc / s;
}

// -------------------------------------------------------------------------
// K2: out[b,x,:] = g_o[b,:]; register-held float4, streaming stores.
// -------------------------------------------------------------------------
constexpr int XROWS = 32;

__global__ __launch_bounds__(256) void k_bcast(float* __restrict__ out) {
    const int bid  = blockIdx.x;          // 0..511
    const int b    = bid >> 6;
    const int slab = bid & 63;

    const float4 val = reinterpret_cast<const float4*>(&g_o[b * H])[threadIdx.x];

    float4* o4 = reinterpret_cast<float4*>(out) +
                 ((size_t)b * X + (size_t)slab * XROWS) * (H / 4) + threadIdx.x;
#pragma unroll
    for (int x = 0; x < XROWS; ++x)
        __stcs(&o4[(size_t)x * (H / 4)], val);
}

// -------------------------------------------------------------------------
// Inputs: q (B,Y,H) f32, k [UNUSED - cancels], v (B,Y,H) f32, W (2H,) f32,
// b [UNUSED - cancels]. Output (B,X,H) f32.
// -------------------------------------------------------------------------
extern "C" void kernel_launch(void* const* d_in, const int* in_sizes, int n_in,
                              void* d_out, int out_size) {
    const float* q = (const float*)d_in[0];
    const float* v = (const float*)d_in[2];
    const float* W = (const float*)d_in[3];
    float* out = (float*)d_out;

    k_part  <<<B * NCH, 256>>>(q, v, W);
    k_reduce<<<B * 4,   256>>>();
    k_bcast <<<B * 64,  256>>>(out);
}